// round 3
// baseline (speedup 1.0000x reference)
#include <cuda_runtime.h>
#include <math.h>

// Problem constants
constexpr int Bn = 2;
constexpr int Ln = 1024;
constexpr int NG = 8;     // "n" groups in x
constexpr int En = 512;
constexpr int Hn = 8;     // attention heads per group
constexpr int HD = 64;    // head dim
constexpr int MR = Bn * Ln * NG;        // 16384 rows for the GEMMs
constexpr int NHEADS = Bn * NG * Hn;    // 128 independent attention problems

// Scratch (static device allocations; no cudaMalloc allowed)
__device__ float g_qkv[(size_t)MR * 3 * En];          // 96 MB
__device__ float g_q[(size_t)NHEADS * Ln * HD];       // 32 MB
__device__ float g_k[(size_t)NHEADS * Ln * HD];       // 32 MB
__device__ float g_v[(size_t)NHEADS * Ln * HD];       // 32 MB
__device__ float g_y[(size_t)MR * En];                // 32 MB
__device__ float g_cos[Bn * Ln * 32];
__device__ float g_sin[Bn * Ln * 32];

// -------------------------------------------------------------------------
// Kernel 1: RoPE cos/sin table. Angle computed like the reference (f32
// product), cosine/sine evaluated in double so large-angle argument
// reduction is exact regardless of compiler fast-math settings.
// -------------------------------------------------------------------------
__global__ void rope_tab_kernel(const int* __restrict__ pos_ids) {
    int idx = blockIdx.x * blockDim.x + threadIdx.x;
    if (idx >= Bn * Ln * 32) return;
    int d = idx & 31;
    int bl = idx >> 5;
    // inv_freq = 10000^(-d/32)
    float inv = (float)exp(-(double)d * (9.210340371976184 / 32.0));
    float ang = (float)pos_ids[bl] * inv;   // f32 product, matching reference
    g_cos[idx] = (float)cos((double)ang);
    g_sin[idx] = (float)sin((double)ang);
}

// -------------------------------------------------------------------------
// Kernel 2: fp32 SGEMM, C[M,N] = A[M,K] @ W[K,N] + bias.
// BM=BN=128, BK=16, 256 threads, 8x8 per thread.
// Assumes M%128==0, N%128==0, K%16==0 (holds for both call sites).
// -------------------------------------------------------------------------
__global__ __launch_bounds__(256) void sgemm_bias_kernel(
    const float* __restrict__ A, const float* __restrict__ W,
    const float* __restrict__ bias, float* __restrict__ C,
    int Ncols, int K)
{
    __shared__ float As[16][128];
    __shared__ float Bs[16][132];   // +4 pad

    int tid = threadIdx.x;
    int bn = blockIdx.x, bm = blockIdx.y;
    const float* Ab = A + (size_t)bm * 128 * K;
    const float* Wb = W + (size_t)bn * 128;

    float acc[8][8];
#pragma unroll
    for (int i = 0; i < 8; i++)
#pragma unroll
        for (int j = 0; j < 8; j++) acc[i][j] = 0.f;

    int aRow = tid >> 2;            // 0..63
    int aCol = (tid & 3) << 2;      // 0,4,8,12
    int bRow = tid >> 5;            // 0..7
    int bCol = (tid & 31) << 2;     // 0..124
    int ty = tid >> 4;              // 0..15
    int tx = tid & 15;              // 0..15

    for (int kt = 0; kt < K; kt += 16) {
        float4 a0 = *(const float4*)(Ab + (size_t)aRow * K + kt + aCol);
        float4 a1 = *(const float4*)(Ab + (size_t)(aRow + 64) * K + kt + aCol);
        float4 b0 = *(const float4*)(Wb + (size_t)(kt + bRow) * Ncols + bCol);
        float4 b1 = *(const float4*)(Wb + (size_t)(kt + bRow + 8) * Ncols + bCol);
        __syncthreads();
        As[aCol + 0][aRow] = a0.x; As[aCol + 1][aRow] = a0.y;
        As[aCol + 2][aRow] = a0.z; As[aCol + 3][aRow] = a0.w;
        As[aCol + 0][aRow + 64] = a1.x; As[aCol + 1][aRow + 64] = a1.y;
        As[aCol + 2][aRow + 64] = a1.z; As[aCol + 3][aRow + 64] = a1.w;
        *(float4*)&Bs[bRow][bCol] = b0;
        *(float4*)&Bs[bRow + 8][bCol] = b1;
        __syncthreads();
#pragma unroll
        for (int k = 0; k < 16; k++) {
            float ar[8], br[8];
            *(float4*)&ar[0] = *(const float4*)&As[k][ty * 8];
            *(float4*)&ar[4] = *(const float4*)&As[k][ty * 8 + 4];
            *(float4*)&br[0] = *(const float4*)&Bs[k][tx * 8];
            *(float4*)&br[4] = *(const float4*)&Bs[k][tx * 8 + 4];
#pragma unroll
            for (int i = 0; i < 8; i++)
#pragma unroll
                for (int j = 0; j < 8; j++) acc[i][j] += ar[i] * br[j];
        }
    }

    int crow = bm * 128 + ty * 8;
    int ccol = bn * 128 + tx * 8;
    float bb[8];
#pragma unroll
    for (int j = 0; j < 8; j++) bb[j] = bias[ccol + j];
#pragma unroll
    for (int i = 0; i < 8; i++) {
        float4 o0 = make_float4(acc[i][0] + bb[0], acc[i][1] + bb[1],
                                acc[i][2] + bb[2], acc[i][3] + bb[3]);
        float4 o1 = make_float4(acc[i][4] + bb[4], acc[i][5] + bb[5],
                                acc[i][6] + bb[6], acc[i][7] + bb[7]);
        *(float4*)(C + (size_t)(crow + i) * Ncols + ccol) = o0;
        *(float4*)(C + (size_t)(crow + i) * Ncols + ccol + 4) = o1;
    }
}

// -------------------------------------------------------------------------
// Kernel 3: apply RoPE to q,k; transpose q,k,v into head-major [bh][l][d].
// One thread per (row r, head h, d<32) pair (handles d and d+32).
// -------------------------------------------------------------------------
__global__ __launch_bounds__(256) void rope_transpose_kernel() {
    int idx = blockIdx.x * blockDim.x + threadIdx.x;  // < MR*8*32
    int d = idx & 31;
    int h = (idx >> 5) & 7;
    int r = idx >> 8;               // row in [0, MR)
    int n = r & 7;
    int bl = r >> 3;                // b*L + l
    int l = bl & (Ln - 1);
    int b = bl >> 10;

    size_t base = (size_t)r * (3 * En) + h * HD;
    float q1 = g_qkv[base + d],            q2 = g_qkv[base + d + 32];
    float k1 = g_qkv[base + En + d],       k2 = g_qkv[base + En + d + 32];
    float v1 = g_qkv[base + 2 * En + d],   v2 = g_qkv[base + 2 * En + d + 32];
    float c = g_cos[bl * 32 + d], s = g_sin[bl * 32 + d];

    int bh = (b * NG + n) * Hn + h;
    size_t o = ((size_t)bh * Ln + l) * HD;
    g_q[o + d]      = q1 * c - q2 * s;
    g_q[o + d + 32] = q2 * c + q1 * s;
    g_k[o + d]      = k1 * c - k2 * s;
    g_k[o + d + 32] = k2 * c + k1 * s;
    g_v[o + d]      = v1;
    g_v[o + d + 32] = v2;
}

// -------------------------------------------------------------------------
// Kernel 4: causal flash attention. Grid = (L/128 q-blocks, 128 heads).
// One thread per q row: q and O accumulator live in registers; K/V tiles
// (64 keys) in smem, read broadcast (uniform address per warp -> no
// conflicts). Online softmax with rare rescale (branch on new max).
// QK dot product uses 4 independent accumulators for ILP (4-cycle FFMA
// RAW latency otherwise serializes a 64-deep chain).
// -------------------------------------------------------------------------
__global__ __launch_bounds__(128) void attn_kernel() {
    int bh = blockIdx.y;
    int qb = blockIdx.x;
    int row = qb * 128 + threadIdx.x;

    __shared__ float ks[64][HD];
    __shared__ float vs[64][HD];

    const float* qp = g_q + ((size_t)bh * Ln + row) * HD;
    float q[HD], o[HD];
#pragma unroll
    for (int d = 0; d < HD; d++) { q[d] = qp[d] * 0.125f; o[d] = 0.f; }
    float m = -INFINITY, sl = 0.f;

    const float* kbase = g_k + (size_t)bh * Ln * HD;
    const float* vbase = g_v + (size_t)bh * Ln * HD;
    int nkb = qb * 2 + 2;   // key blocks of 64 needed for causal coverage

    for (int kb = 0; kb < nkb; kb++) {
        __syncthreads();
        const float4* ksrc = (const float4*)(kbase + (size_t)kb * 64 * HD);
        const float4* vsrc = (const float4*)(vbase + (size_t)kb * 64 * HD);
        float4* kdst = (float4*)&ks[0][0];
        float4* vdst = (float4*)&vs[0][0];
#pragma unroll
        for (int i = 0; i < 8; i++) {
            kdst[threadIdx.x + i * 128] = ksrc[threadIdx.x + i * 128];
            vdst[threadIdx.x + i * 128] = vsrc[threadIdx.x + i * 128];
        }
        __syncthreads();

        int jmax = row - kb * 64 + 1;
        if (jmax > 64) jmax = 64;
        for (int j = 0; j < jmax; j++) {
            float s0 = 0.f, s1 = 0.f, s2 = 0.f, s3 = 0.f;
#pragma unroll
            for (int d = 0; d < HD; d += 4) {
                s0 += q[d + 0] * ks[j][d + 0];
                s1 += q[d + 1] * ks[j][d + 1];
                s2 += q[d + 2] * ks[j][d + 2];
                s3 += q[d + 3] * ks[j][d + 3];
            }
            float s_ = (s0 + s1) + (s2 + s3);
            if (s_ > m) {
                float corr = expf(m - s_);
                m = s_;
                sl *= corr;
#pragma unroll
                for (int d = 0; d < HD; d++) o[d] *= corr;
            }
            float p = expf(s_ - m);
            sl += p;
#pragma unroll
            for (int d = 0; d < HD; d++) o[d] += p * vs[j][d];
        }
    }

    float invs = 1.f / sl;
    int b = bh >> 6, n = (bh >> 3) & 7, h = bh & 7;
    size_t r = ((size_t)(b * Ln + row)) * NG + n;
    float* yp = g_y + r * En + h * HD;
#pragma unroll
    for (int d = 0; d < HD; d++) yp[d] = o[d] * invs;
}

// -------------------------------------------------------------------------
// Launch: 5 kernels on the default stream (graph-capturable; no sync, no
// allocation; scratch lives in __device__ globals).
// -------------------------------------------------------------------------
extern "C" void kernel_launch(void* const* d_in, const int* in_sizes, int n_in,
                              void* d_out, int out_size) {
    const float* x      = (const float*)d_in[0];
    const int*   pos    = (const int*)d_in[1];
    const float* w_attn = (const float*)d_in[2];
    const float* b_attn = (const float*)d_in[3];
    const float* w_proj = (const float*)d_in[4];
    const float* b_proj = (const float*)d_in[5];
    float* out = (float*)d_out;

    float *qkv_ptr, *y_ptr;
    cudaGetSymbolAddress((void**)&qkv_ptr, g_qkv);
    cudaGetSymbolAddress((void**)&y_ptr, g_y);

    // 1) cos/sin table: 65536 entries
    rope_tab_kernel<<<(Bn * Ln * 32 + 255) / 256, 256>>>(pos);
    // 2) QKV GEMM: 16384 x 1536, K=512
    sgemm_bias_kernel<<<dim3(1536 / 128, MR / 128), 256>>>(x, w_attn, b_attn,
                                                           qkv_ptr, 3 * En, En);
    // 3) RoPE + transpose into head-major scratch
    rope_transpose_kernel<<<(MR * 256) / 256, 256>>>();
    // 4) attention: 8 q-blocks x 128 heads
    attn_kernel<<<dim3(Ln / 128, NHEADS), 128>>>();
    // 5) output projection: 16384 x 512, K=512
    sgemm_bias_kernel<<<dim3(En / 128, MR / 128), 256>>>(y_ptr, w_proj, b_proj,
                                                         out, En, En);
}

// round 8
// speedup vs baseline: 2.6105x; 2.6105x over previous
#include <cuda_runtime.h>
#include <math.h>
#include <stdint.h>

// Problem constants
constexpr int Bn = 2;
constexpr int Ln = 1024;
constexpr int NG = 8;
constexpr int En = 512;
constexpr int Hn = 8;
constexpr int HD = 64;
constexpr int MR = Bn * Ln * NG;        // 16384 GEMM rows
constexpr int NHEADS = Bn * NG * Hn;    // 128 attention heads

// Scratch (__device__ globals; no cudaMalloc allowed)
__device__ float g_qkv[(size_t)MR * 3 * En];
__device__ float g_q[(size_t)NHEADS * Ln * HD];
__device__ float g_k[(size_t)NHEADS * Ln * HD];
__device__ float g_v[(size_t)NHEADS * Ln * HD];
__device__ float g_y[(size_t)MR * En];
__device__ float g_cos[Bn * Ln * 32];
__device__ float g_sin[Bn * Ln * 32];

__device__ __forceinline__ uint32_t f2tf32(float x) {
    uint32_t u;
    asm("cvt.rna.tf32.f32 %0, %1;" : "=r"(u) : "f"(x));
    return u;
}
__device__ __forceinline__ void mma_tf32(float c[4], uint32_t a0, uint32_t a1,
                                         uint32_t a2, uint32_t a3,
                                         uint32_t b0, uint32_t b1) {
    asm volatile(
        "mma.sync.aligned.m16n8k8.row.col.f32.tf32.tf32.f32 "
        "{%0,%1,%2,%3}, {%4,%5,%6,%7}, {%8,%9}, {%0,%1,%2,%3};"
        : "+f"(c[0]), "+f"(c[1]), "+f"(c[2]), "+f"(c[3])
        : "r"(a0), "r"(a1), "r"(a2), "r"(a3), "r"(b0), "r"(b1));
}

// -------------------------------------------------------------------------
// Kernel 1: RoPE cos/sin table (double-precision trig: exact arg reduction)
// -------------------------------------------------------------------------
__global__ void rope_tab_kernel(const int* __restrict__ pos_ids) {
    int idx = blockIdx.x * blockDim.x + threadIdx.x;
    if (idx >= Bn * Ln * 32) return;
    int d = idx & 31;
    int bl = idx >> 5;
    float inv = (float)exp(-(double)d * (9.210340371976184 / 32.0));
    float ang = (float)pos_ids[bl] * inv;
    g_cos[idx] = (float)cos((double)ang);
    g_sin[idx] = (float)sin((double)ang);
}

// -------------------------------------------------------------------------
// Kernel 2: tf32 mma.sync GEMM.  C[M,Ncols] = A[M,K] @ W[K,Ncols] + bias
// BM=BN=128, BK=16, 256 threads = 8 warps (4 M x 2 N); warp tile 32x64.
// -------------------------------------------------------------------------
__global__ __launch_bounds__(256) void mma_gemm_kernel(
    const float* __restrict__ A, const float* __restrict__ W,
    const float* __restrict__ bias, float* __restrict__ C,
    int Ncols, int K)
{
    __shared__ uint32_t As[16][132];   // [k][row], +4 pad
    __shared__ uint32_t Bs[16][132];   // [k][n],  +4 pad

    int tid = threadIdx.x;
    int bn = blockIdx.x, bm = blockIdx.y;
    const float* Ab = A + (size_t)bm * 128 * K;
    const float* Wb = W + (size_t)bn * 128;

    int aRow = tid >> 2;            // 0..63
    int aCol = (tid & 3) << 2;      // 0,4,8,12
    int bRow = tid >> 5;            // 0..7
    int bCol = (tid & 31) << 2;     // 0..124

    int warp = tid >> 5, lane = tid & 31;
    int wm = warp >> 1;
    int wn = warp & 1;
    int g = lane >> 2, t = lane & 3;
    int rbase = wm * 32;
    int nbase = wn * 64;

    float acc[2][8][4];
#pragma unroll
    for (int mf = 0; mf < 2; mf++)
#pragma unroll
        for (int nf = 0; nf < 8; nf++)
#pragma unroll
            for (int i = 0; i < 4; i++) acc[mf][nf][i] = 0.f;

    for (int kt = 0; kt < K; kt += 16) {
        float4 a0 = *(const float4*)(Ab + (size_t)aRow * K + kt + aCol);
        float4 a1 = *(const float4*)(Ab + (size_t)(aRow + 64) * K + kt + aCol);
        float4 b0 = *(const float4*)(Wb + (size_t)(kt + bRow) * Ncols + bCol);
        float4 b1 = *(const float4*)(Wb + (size_t)(kt + bRow + 8) * Ncols + bCol);
        __syncthreads();
        As[aCol + 0][aRow] = f2tf32(a0.x); As[aCol + 1][aRow] = f2tf32(a0.y);
        As[aCol + 2][aRow] = f2tf32(a0.z); As[aCol + 3][aRow] = f2tf32(a0.w);
        As[aCol + 0][aRow + 64] = f2tf32(a1.x); As[aCol + 1][aRow + 64] = f2tf32(a1.y);
        As[aCol + 2][aRow + 64] = f2tf32(a1.z); As[aCol + 3][aRow + 64] = f2tf32(a1.w);
        Bs[bRow][bCol + 0] = f2tf32(b0.x); Bs[bRow][bCol + 1] = f2tf32(b0.y);
        Bs[bRow][bCol + 2] = f2tf32(b0.z); Bs[bRow][bCol + 3] = f2tf32(b0.w);
        Bs[bRow + 8][bCol + 0] = f2tf32(b1.x); Bs[bRow + 8][bCol + 1] = f2tf32(b1.y);
        Bs[bRow + 8][bCol + 2] = f2tf32(b1.z); Bs[bRow + 8][bCol + 3] = f2tf32(b1.w);
        __syncthreads();

#pragma unroll
        for (int ks = 0; ks < 16; ks += 8) {
            uint32_t af[2][4];
#pragma unroll
            for (int mf = 0; mf < 2; mf++) {
                int r0 = rbase + mf * 16 + g;
                af[mf][0] = As[ks + t][r0];
                af[mf][1] = As[ks + t][r0 + 8];
                af[mf][2] = As[ks + t + 4][r0];
                af[mf][3] = As[ks + t + 4][r0 + 8];
            }
            uint32_t bf[8][2];
#pragma unroll
            for (int nf = 0; nf < 8; nf++) {
                int c0 = nbase + nf * 8 + g;
                bf[nf][0] = Bs[ks + t][c0];
                bf[nf][1] = Bs[ks + t + 4][c0];
            }
#pragma unroll
            for (int mf = 0; mf < 2; mf++)
#pragma unroll
                for (int nf = 0; nf < 8; nf++)
                    mma_tf32(acc[mf][nf], af[mf][0], af[mf][1], af[mf][2],
                             af[mf][3], bf[nf][0], bf[nf][1]);
        }
    }

#pragma unroll
    for (int mf = 0; mf < 2; mf++) {
        int row0 = bm * 128 + rbase + mf * 16 + g;
#pragma unroll
        for (int nf = 0; nf < 8; nf++) {
            int col = bn * 128 + nbase + nf * 8 + 2 * t;
            float bx = bias[col], by = bias[col + 1];
            float2 o0 = make_float2(acc[mf][nf][0] + bx, acc[mf][nf][1] + by);
            float2 o1 = make_float2(acc[mf][nf][2] + bx, acc[mf][nf][3] + by);
            *(float2*)(C + (size_t)row0 * Ncols + col) = o0;
            *(float2*)(C + (size_t)(row0 + 8) * Ncols + col) = o1;
        }
    }
}

// -------------------------------------------------------------------------
// Kernel 3: RoPE + transpose q,k,v into head-major [bh][l][d]
// -------------------------------------------------------------------------
__global__ __launch_bounds__(256) void rope_transpose_kernel() {
    int idx = blockIdx.x * blockDim.x + threadIdx.x;
    int d = idx & 31;
    int h = (idx >> 5) & 7;
    int r = idx >> 8;
    int n = r & 7;
    int bl = r >> 3;
    int l = bl & (Ln - 1);
    int b = bl >> 10;

    size_t base = (size_t)r * (3 * En) + h * HD;
    float q1 = g_qkv[base + d],          q2 = g_qkv[base + d + 32];
    float k1 = g_qkv[base + En + d],     k2 = g_qkv[base + En + d + 32];
    float v1 = g_qkv[base + 2 * En + d], v2 = g_qkv[base + 2 * En + d + 32];
    float c = g_cos[bl * 32 + d], s = g_sin[bl * 32 + d];

    int bh = (b * NG + n) * Hn + h;
    size_t o = ((size_t)bh * Ln + l) * HD;
    g_q[o + d]      = q1 * c - q2 * s;
    g_q[o + d + 32] = q2 * c + q1 * s;
    g_k[o + d]      = k1 * c - k2 * s;
    g_k[o + d + 32] = k2 * c + k1 * s;
    g_v[o + d]      = v1;
    g_v[o + d + 32] = v2;
}

// -------------------------------------------------------------------------
// Kernel 4: tensor-core causal flash attention (tf32 mma.sync).
// Grid (Ln/64, 128 heads), 128 threads = 4 warps, warp = 16 q-rows (m16).
// Smem: QPs[64][68] (Q staging, then reused per-warp for P), Ks[64][68],
// Vs[64][72]  (pads chosen for conflict-free fragment LDS). 53 KB dynamic.
// Causal handled by warp-uniform frag bounds on the diagonal tile +
// elementwise mask; all register-array loops fully unrolled with uniform
// guards (no dynamic indexing).
// -------------------------------------------------------------------------
__global__ __launch_bounds__(128) void attn_mma_kernel() {
    extern __shared__ uint32_t dynsmem[];
    uint32_t (*QPs)[68] = (uint32_t(*)[68])dynsmem;               // 64x68
    uint32_t (*Ks)[68]  = (uint32_t(*)[68])(dynsmem + 64 * 68);   // 64x68
    uint32_t (*Vs)[72]  = (uint32_t(*)[72])(dynsmem + 2 * 64 * 68); // 64x72

    int qb = blockIdx.x, bh = blockIdx.y;
    int tid = threadIdx.x, warp = tid >> 5, lane = tid & 31;
    int g = lane >> 2, t = lane & 3;

    const float* qp = g_q + ((size_t)bh * Ln + qb * 64) * HD;
    const float* kp = g_k + (size_t)bh * Ln * HD;
    const float* vp = g_v + (size_t)bh * Ln * HD;

    // Stage Q tile (x0.125 exact, tf32) into QPs
    for (int i = tid; i < 64 * 16; i += 128) {
        int row = i >> 4, c = (i & 15) * 4;
        float4 v = *(const float4*)(qp + (size_t)row * HD + c);
        QPs[row][c + 0] = f2tf32(v.x * 0.125f);
        QPs[row][c + 1] = f2tf32(v.y * 0.125f);
        QPs[row][c + 2] = f2tf32(v.z * 0.125f);
        QPs[row][c + 3] = f2tf32(v.w * 0.125f);
    }
    __syncthreads();

    int r0 = warp * 16 + g;          // warp-local rows r0, r0+8
    uint32_t Qf[8][4];
#pragma unroll
    for (int kc = 0; kc < 8; kc++) {
        Qf[kc][0] = QPs[r0][kc * 8 + t];
        Qf[kc][1] = QPs[r0 + 8][kc * 8 + t];
        Qf[kc][2] = QPs[r0][kc * 8 + t + 4];
        Qf[kc][3] = QPs[r0 + 8][kc * 8 + t + 4];
    }

    float Of[8][4];
#pragma unroll
    for (int nf = 0; nf < 8; nf++)
#pragma unroll
        for (int i = 0; i < 4; i++) Of[nf][i] = 0.f;
    float m0 = -1e30f, m1 = -1e30f, l0 = 0.f, l1 = 0.f;

    for (int kb = 0; kb <= qb; kb++) {
        __syncthreads();
        for (int i = tid; i < 64 * 16; i += 128) {
            int row = i >> 4, c = (i & 15) * 4;
            float4 kv = *(const float4*)(kp + (size_t)(kb * 64 + row) * HD + c);
            float4 vv = *(const float4*)(vp + (size_t)(kb * 64 + row) * HD + c);
            Ks[row][c + 0] = f2tf32(kv.x); Ks[row][c + 1] = f2tf32(kv.y);
            Ks[row][c + 2] = f2tf32(kv.z); Ks[row][c + 3] = f2tf32(kv.w);
            Vs[row][c + 0] = f2tf32(vv.x); Vs[row][c + 1] = f2tf32(vv.y);
            Vs[row][c + 2] = f2tf32(vv.z); Vs[row][c + 3] = f2tf32(vv.w);
        }
        __syncthreads();

        bool diag = (kb == qb);
        int nfmax = diag ? (warp * 2 + 2) : 8;   // warp-uniform

        // S = Q K^T
        float Sf[8][4];
#pragma unroll
        for (int nf = 0; nf < 8; nf++) {
            if (nf < nfmax) {
                Sf[nf][0] = 0.f; Sf[nf][1] = 0.f; Sf[nf][2] = 0.f; Sf[nf][3] = 0.f;
#pragma unroll
                for (int kc = 0; kc < 8; kc++) {
                    uint32_t b0 = Ks[nf * 8 + g][kc * 8 + t];
                    uint32_t b1 = Ks[nf * 8 + g][kc * 8 + t + 4];
                    mma_tf32(Sf[nf], Qf[kc][0], Qf[kc][1], Qf[kc][2], Qf[kc][3],
                             b0, b1);
                }
                if (diag) {
                    int rl0 = warp * 16 + g, rl1 = rl0 + 8, c0 = nf * 8 + 2 * t;
                    if (c0 > rl0)     Sf[nf][0] = -1e30f;
                    if (c0 + 1 > rl0) Sf[nf][1] = -1e30f;
                    if (c0 > rl1)     Sf[nf][2] = -1e30f;
                    if (c0 + 1 > rl1) Sf[nf][3] = -1e30f;
                }
            }
        }

        // Online softmax (rows r0, r0+8); quad-shfl row reductions
        float tm0 = -1e30f, tm1 = -1e30f;
#pragma unroll
        for (int nf = 0; nf < 8; nf++)
            if (nf < nfmax) {
                tm0 = fmaxf(tm0, fmaxf(Sf[nf][0], Sf[nf][1]));
                tm1 = fmaxf(tm1, fmaxf(Sf[nf][2], Sf[nf][3]));
            }
        tm0 = fmaxf(tm0, __shfl_xor_sync(0xffffffffu, tm0, 1));
        tm0 = fmaxf(tm0, __shfl_xor_sync(0xffffffffu, tm0, 2));
        tm1 = fmaxf(tm1, __shfl_xor_sync(0xffffffffu, tm1, 1));
        tm1 = fmaxf(tm1, __shfl_xor_sync(0xffffffffu, tm1, 2));
        float mn0 = fmaxf(m0, tm0), mn1 = fmaxf(m1, tm1);
        float cr0 = __expf(m0 - mn0), cr1 = __expf(m1 - mn1);
        m0 = mn0; m1 = mn1;

        float rs0 = 0.f, rs1 = 0.f;
#pragma unroll
        for (int nf = 0; nf < 8; nf++)
            if (nf < nfmax) {
                float p0 = __expf(Sf[nf][0] - m0);
                float p1 = __expf(Sf[nf][1] - m0);
                float p2 = __expf(Sf[nf][2] - m1);
                float p3 = __expf(Sf[nf][3] - m1);
                rs0 += p0 + p1; rs1 += p2 + p3;
                int c = nf * 8 + 2 * t;
                QPs[r0][c]         = f2tf32(p0);
                QPs[r0][c + 1]     = f2tf32(p1);
                QPs[r0 + 8][c]     = f2tf32(p2);
                QPs[r0 + 8][c + 1] = f2tf32(p3);
            }
        rs0 += __shfl_xor_sync(0xffffffffu, rs0, 1);
        rs0 += __shfl_xor_sync(0xffffffffu, rs0, 2);
        rs1 += __shfl_xor_sync(0xffffffffu, rs1, 1);
        rs1 += __shfl_xor_sync(0xffffffffu, rs1, 2);
        l0 = l0 * cr0 + rs0;
        l1 = l1 * cr1 + rs1;
#pragma unroll
        for (int nf = 0; nf < 8; nf++) {
            Of[nf][0] *= cr0; Of[nf][1] *= cr0;
            Of[nf][2] *= cr1; Of[nf][3] *= cr1;
        }
        __syncwarp();   // P stores visible to fragment loads (cross-lane)

        // O += P V
        int kcmax = diag ? (warp * 2 + 2) : 8;   // warp-uniform
#pragma unroll
        for (int kc = 0; kc < 8; kc++)
            if (kc < kcmax) {
                uint32_t a0 = QPs[r0][kc * 8 + t];
                uint32_t a1 = QPs[r0 + 8][kc * 8 + t];
                uint32_t a2 = QPs[r0][kc * 8 + t + 4];
                uint32_t a3 = QPs[r0 + 8][kc * 8 + t + 4];
#pragma unroll
                for (int nf = 0; nf < 8; nf++) {
                    uint32_t b0 = Vs[kc * 8 + t][nf * 8 + g];
                    uint32_t b1 = Vs[kc * 8 + t + 4][nf * 8 + g];
                    mma_tf32(Of[nf], a0, a1, a2, a3, b0, b1);
                }
            }
        __syncwarp();   // done with this tile's QPs before next tile reuse
    }

    // Normalize and write to g_y in [b,l,n][h*64+d] layout
    float il0 = 1.f / l0, il1 = 1.f / l1;
    int b = bh >> 6, n = (bh >> 3) & 7, h = bh & 7;
    int q0 = qb * 64 + warp * 16 + g;
    float* y0 = g_y + ((size_t)(b * Ln + q0) * NG + n) * En + h * HD;
    float* y1 = g_y + ((size_t)(b * Ln + q0 + 8) * NG + n) * En + h * HD;
#pragma unroll
    for (int nf = 0; nf < 8; nf++) {
        int c = nf * 8 + 2 * t;
        *(float2*)(y0 + c) = make_float2(Of[nf][0] * il0, Of[nf][1] * il0);
        *(float2*)(y1 + c) = make_float2(Of[nf][2] * il1, Of[nf][3] * il1);
    }
}

constexpr int ATTN_SMEM = (64 * 68 * 2 + 64 * 72) * 4;   // 53248 bytes

// -------------------------------------------------------------------------
extern "C" void kernel_launch(void* const* d_in, const int* in_sizes, int n_in,
                              void* d_out, int out_size) {
    const float* x      = (const float*)d_in[0];
    const int*   pos    = (const int*)d_in[1];
    const float* w_attn = (const float*)d_in[2];
    const float* b_attn = (const float*)d_in[3];
    const float* w_proj = (const float*)d_in[4];
    const float* b_proj = (const float*)d_in[5];
    float* out = (float*)d_out;

    float *qkv_ptr, *y_ptr;
    cudaGetSymbolAddress((void**)&qkv_ptr, g_qkv);
    cudaGetSymbolAddress((void**)&y_ptr, g_y);
    cudaFuncSetAttribute(attn_mma_kernel,
                         cudaFuncAttributeMaxDynamicSharedMemorySize, ATTN_SMEM);

    // 1) cos/sin table
    rope_tab_kernel<<<(Bn * Ln * 32 + 255) / 256, 256>>>(pos);
    // 2) QKV GEMM (tf32 mma.sync): [16384,512] @ [512,1536]
    mma_gemm_kernel<<<dim3(3 * En / 128, MR / 128), 256>>>(x, w_attn, b_attn,
                                                           qkv_ptr, 3 * En, En);
    // 3) RoPE + transpose into head-major scratch
    rope_transpose_kernel<<<(MR * 256) / 256, 256>>>();
    // 4) tensor-core flash attention: 16 q-blocks x 128 heads
    attn_mma_kernel<<<dim3(Ln / 64, NHEADS), 128, ATTN_SMEM>>>();
    // 5) output projection (tf32 mma.sync): [16384,512] @ [512,512]
    mma_gemm_kernel<<<dim3(En / 128, MR / 128), 256>>>(y_ptr, w_proj, b_proj,
                                                       out, En, En);
}

// round 13
// speedup vs baseline: 2.6437x; 1.0127x over previous
#include <cuda_runtime.h>
#include <math.h>
#include <stdint.h>

// Problem constants
constexpr int Bn = 2;
constexpr int Ln = 1024;
constexpr int NG = 8;
constexpr int En = 512;
constexpr int Hn = 8;
constexpr int HD = 64;
constexpr int MR = Bn * Ln * NG;        // 16384 GEMM rows
constexpr int NHEADS = Bn * NG * Hn;    // 128 attention heads

// Scratch (__device__ globals; no cudaMalloc allowed)
__device__ float g_qkv[(size_t)MR * 3 * En];
__device__ float g_q[(size_t)NHEADS * Ln * HD];
__device__ float g_k[(size_t)NHEADS * Ln * HD];
__device__ float g_v[(size_t)NHEADS * Ln * HD];
__device__ float g_y[(size_t)MR * En];
__device__ float g_cos[Bn * Ln * 32];
__device__ float g_sin[Bn * Ln * 32];

__device__ __forceinline__ uint32_t f2tf32(float x) {
    uint32_t u;
    asm("cvt.rna.tf32.f32 %0, %1;" : "=r"(u) : "f"(x));
    return u;
}
__device__ __forceinline__ void mma_tf32(float c[4], uint32_t a0, uint32_t a1,
                                         uint32_t a2, uint32_t a3,
                                         uint32_t b0, uint32_t b1) {
    asm volatile(
        "mma.sync.aligned.m16n8k8.row.col.f32.tf32.tf32.f32 "
        "{%0,%1,%2,%3}, {%4,%5,%6,%7}, {%8,%9}, {%0,%1,%2,%3};"
        : "+f"(c[0]), "+f"(c[1]), "+f"(c[2]), "+f"(c[3])
        : "r"(a0), "r"(a1), "r"(a2), "r"(a3), "r"(b0), "r"(b1));
}

// -------------------------------------------------------------------------
// Kernel 1: RoPE cos/sin table (double-precision trig: exact arg reduction)
// -------------------------------------------------------------------------
__global__ void rope_tab_kernel(const int* __restrict__ pos_ids) {
    int idx = blockIdx.x * blockDim.x + threadIdx.x;
    if (idx >= Bn * Ln * 32) return;
    int d = idx & 31;
    int bl = idx >> 5;
    float inv = (float)exp(-(double)d * (9.210340371976184 / 32.0));
    float ang = (float)pos_ids[bl] * inv;
    g_cos[idx] = (float)cos((double)ang);
    g_sin[idx] = (float)sin((double)ang);
}

// -------------------------------------------------------------------------
// Kernel 2: tf32 mma.sync GEMM with register-prefetch double buffering.
// C[M,Ncols] = A[M,K] @ W[K,Ncols] + bias
// BM=BN=128, BK=16, 256 threads = 8 warps (4 M x 2 N); warp tile 32x64.
// Per iter: sync -> STS(convert, current) -> sync -> issue LDG(next)
// -> compute current (LDG latency hidden behind compute).
// -------------------------------------------------------------------------
__global__ __launch_bounds__(256) void mma_gemm_kernel(
    const float* __restrict__ A, const float* __restrict__ W,
    const float* __restrict__ bias, float* __restrict__ C,
    int Ncols, int K)
{
    __shared__ uint32_t As[16][132];   // [k][row], +4 pad
    __shared__ uint32_t Bs[16][132];   // [k][n],  +4 pad

    int tid = threadIdx.x;
    int bn = blockIdx.x, bm = blockIdx.y;
    const float* Ab = A + (size_t)bm * 128 * K;
    const float* Wb = W + (size_t)bn * 128;

    int aRow = tid >> 2;            // 0..63
    int aCol = (tid & 3) << 2;      // 0,4,8,12
    int bRow = tid >> 5;            // 0..7
    int bCol = (tid & 31) << 2;     // 0..124

    int warp = tid >> 5, lane = tid & 31;
    int wm = warp >> 1;
    int wn = warp & 1;
    int g = lane >> 2, t = lane & 3;
    int rbase = wm * 32;
    int nbase = wn * 64;

    float acc[2][8][4];
#pragma unroll
    for (int mf = 0; mf < 2; mf++)
#pragma unroll
        for (int nf = 0; nf < 8; nf++)
#pragma unroll
            for (int i = 0; i < 4; i++) acc[mf][nf][i] = 0.f;

    // Prefetch first tile into registers
    float4 a0 = *(const float4*)(Ab + (size_t)aRow * K + aCol);
    float4 a1 = *(const float4*)(Ab + (size_t)(aRow + 64) * K + aCol);
    float4 b0 = *(const float4*)(Wb + (size_t)bRow * Ncols + bCol);
    float4 b1 = *(const float4*)(Wb + (size_t)(bRow + 8) * Ncols + bCol);

    for (int kt = 0; kt < K; kt += 16) {
        __syncthreads();    // previous compute done: smem reusable
        As[aCol + 0][aRow] = f2tf32(a0.x); As[aCol + 1][aRow] = f2tf32(a0.y);
        As[aCol + 2][aRow] = f2tf32(a0.z); As[aCol + 3][aRow] = f2tf32(a0.w);
        As[aCol + 0][aRow + 64] = f2tf32(a1.x); As[aCol + 1][aRow + 64] = f2tf32(a1.y);
        As[aCol + 2][aRow + 64] = f2tf32(a1.z); As[aCol + 3][aRow + 64] = f2tf32(a1.w);
        Bs[bRow][bCol + 0] = f2tf32(b0.x); Bs[bRow][bCol + 1] = f2tf32(b0.y);
        Bs[bRow][bCol + 2] = f2tf32(b0.z); Bs[bRow][bCol + 3] = f2tf32(b0.w);
        Bs[bRow + 8][bCol + 0] = f2tf32(b1.x); Bs[bRow + 8][bCol + 1] = f2tf32(b1.y);
        Bs[bRow + 8][bCol + 2] = f2tf32(b1.z); Bs[bRow + 8][bCol + 3] = f2tf32(b1.w);
        __syncthreads();

        // Issue next-tile loads (clamped on last iter; values unused then)
        int ktn = (kt + 16 < K) ? (kt + 16) : 0;
        a0 = *(const float4*)(Ab + (size_t)aRow * K + ktn + aCol);
        a1 = *(const float4*)(Ab + (size_t)(aRow + 64) * K + ktn + aCol);
        b0 = *(const float4*)(Wb + (size_t)(ktn + bRow) * Ncols + bCol);
        b1 = *(const float4*)(Wb + (size_t)(ktn + bRow + 8) * Ncols + bCol);

#pragma unroll
        for (int ks = 0; ks < 16; ks += 8) {
            uint32_t af[2][4];
#pragma unroll
            for (int mf = 0; mf < 2; mf++) {
                int r0 = rbase + mf * 16 + g;
                af[mf][0] = As[ks + t][r0];
                af[mf][1] = As[ks + t][r0 + 8];
                af[mf][2] = As[ks + t + 4][r0];
                af[mf][3] = As[ks + t + 4][r0 + 8];
            }
            uint32_t bf[8][2];
#pragma unroll
            for (int nf = 0; nf < 8; nf++) {
                int c0 = nbase + nf * 8 + g;
                bf[nf][0] = Bs[ks + t][c0];
                bf[nf][1] = Bs[ks + t + 4][c0];
            }
#pragma unroll
            for (int mf = 0; mf < 2; mf++)
#pragma unroll
                for (int nf = 0; nf < 8; nf++)
                    mma_tf32(acc[mf][nf], af[mf][0], af[mf][1], af[mf][2],
                             af[mf][3], bf[nf][0], bf[nf][1]);
        }
    }

#pragma unroll
    for (int mf = 0; mf < 2; mf++) {
        int row0 = bm * 128 + rbase + mf * 16 + g;
#pragma unroll
        for (int nf = 0; nf < 8; nf++) {
            int col = bn * 128 + nbase + nf * 8 + 2 * t;
            float bx = bias[col], by = bias[col + 1];
            float2 o0 = make_float2(acc[mf][nf][0] + bx, acc[mf][nf][1] + by);
            float2 o1 = make_float2(acc[mf][nf][2] + bx, acc[mf][nf][3] + by);
            *(float2*)(C + (size_t)row0 * Ncols + col) = o0;
            *(float2*)(C + (size_t)(row0 + 8) * Ncols + col) = o1;
        }
    }
}

// -------------------------------------------------------------------------
// Kernel 3: RoPE + transpose q,k,v into head-major [bh][l][d]
// -------------------------------------------------------------------------
__global__ __launch_bounds__(256) void rope_transpose_kernel() {
    int idx = blockIdx.x * blockDim.x + threadIdx.x;
    int d = idx & 31;
    int h = (idx >> 5) & 7;
    int r = idx >> 8;
    int n = r & 7;
    int bl = r >> 3;
    int l = bl & (Ln - 1);
    int b = bl >> 10;

    size_t base = (size_t)r * (3 * En) + h * HD;
    float q1 = g_qkv[base + d],          q2 = g_qkv[base + d + 32];
    float k1 = g_qkv[base + En + d],     k2 = g_qkv[base + En + d + 32];
    float v1 = g_qkv[base + 2 * En + d], v2 = g_qkv[base + 2 * En + d + 32];
    float c = g_cos[bl * 32 + d], s = g_sin[bl * 32 + d];

    int bh = (b * NG + n) * Hn + h;
    size_t o = ((size_t)bh * Ln + l) * HD;
    g_q[o + d]      = q1 * c - q2 * s;
    g_q[o + d + 32] = q2 * c + q1 * s;
    g_k[o + d]      = k1 * c - k2 * s;
    g_k[o + d + 32] = k2 * c + k1 * s;
    g_v[o + d]      = v1;
    g_v[o + d + 32] = v2;
}

// -------------------------------------------------------------------------
// Kernel 4: tensor-core causal flash attention (tf32 mma.sync).
// Unchanged from the 236.6us passing version (clean attribution).
// -------------------------------------------------------------------------
__global__ __launch_bounds__(128) void attn_mma_kernel() {
    extern __shared__ uint32_t dynsmem[];
    uint32_t (*QPs)[68] = (uint32_t(*)[68])dynsmem;               // 64x68
    uint32_t (*Ks)[68]  = (uint32_t(*)[68])(dynsmem + 64 * 68);   // 64x68
    uint32_t (*Vs)[72]  = (uint32_t(*)[72])(dynsmem + 2 * 64 * 68); // 64x72

    int qb = blockIdx.x, bh = blockIdx.y;
    int tid = threadIdx.x, warp = tid >> 5, lane = tid & 31;
    int g = lane >> 2, t = lane & 3;

    const float* qp = g_q + ((size_t)bh * Ln + qb * 64) * HD;
    const float* kp = g_k + (size_t)bh * Ln * HD;
    const float* vp = g_v + (size_t)bh * Ln * HD;

    for (int i = tid; i < 64 * 16; i += 128) {
        int row = i >> 4, c = (i & 15) * 4;
        float4 v = *(const float4*)(qp + (size_t)row * HD + c);
        QPs[row][c + 0] = f2tf32(v.x * 0.125f);
        QPs[row][c + 1] = f2tf32(v.y * 0.125f);
        QPs[row][c + 2] = f2tf32(v.z * 0.125f);
        QPs[row][c + 3] = f2tf32(v.w * 0.125f);
    }
    __syncthreads();

    int r0 = warp * 16 + g;
    uint32_t Qf[8][4];
#pragma unroll
    for (int kc = 0; kc < 8; kc++) {
        Qf[kc][0] = QPs[r0][kc * 8 + t];
        Qf[kc][1] = QPs[r0 + 8][kc * 8 + t];
        Qf[kc][2] = QPs[r0][kc * 8 + t + 4];
        Qf[kc][3] = QPs[r0 + 8][kc * 8 + t + 4];
    }

    float Of[8][4];
#pragma unroll
    for (int nf = 0; nf < 8; nf++)
#pragma unroll
        for (int i = 0; i < 4; i++) Of[nf][i] = 0.f;
    float m0 = -1e30f, m1 = -1e30f, l0 = 0.f, l1 = 0.f;

    for (int kb = 0; kb <= qb; kb++) {
        __syncthreads();
        for (int i = tid; i < 64 * 16; i += 128) {
            int row = i >> 4, c = (i & 15) * 4;
            float4 kv = *(const float4*)(kp + (size_t)(kb * 64 + row) * HD + c);
            float4 vv = *(const float4*)(vp + (size_t)(kb * 64 + row) * HD + c);
            Ks[row][c + 0] = f2tf32(kv.x); Ks[row][c + 1] = f2tf32(kv.y);
            Ks[row][c + 2] = f2tf32(kv.z); Ks[row][c + 3] = f2tf32(kv.w);
            Vs[row][c + 0] = f2tf32(vv.x); Vs[row][c + 1] = f2tf32(vv.y);
            Vs[row][c + 2] = f2tf32(vv.z); Vs[row][c + 3] = f2tf32(vv.w);
        }
        __syncthreads();

        bool diag = (kb == qb);
        int nfmax = diag ? (warp * 2 + 2) : 8;

        float Sf[8][4];
#pragma unroll
        for (int nf = 0; nf < 8; nf++) {
            if (nf < nfmax) {
                Sf[nf][0] = 0.f; Sf[nf][1] = 0.f; Sf[nf][2] = 0.f; Sf[nf][3] = 0.f;
#pragma unroll
                for (int kc = 0; kc < 8; kc++) {
                    uint32_t b0 = Ks[nf * 8 + g][kc * 8 + t];
                    uint32_t b1 = Ks[nf * 8 + g][kc * 8 + t + 4];
                    mma_tf32(Sf[nf], Qf[kc][0], Qf[kc][1], Qf[kc][2], Qf[kc][3],
                             b0, b1);
                }
                if (diag) {
                    int rl0 = warp * 16 + g, rl1 = rl0 + 8, c0 = nf * 8 + 2 * t;
                    if (c0 > rl0)     Sf[nf][0] = -1e30f;
                    if (c0 + 1 > rl0) Sf[nf][1] = -1e30f;
                    if (c0 > rl1)     Sf[nf][2] = -1e30f;
                    if (c0 + 1 > rl1) Sf[nf][3] = -1e30f;
                }
            }
        }

        float tm0 = -1e30f, tm1 = -1e30f;
#pragma unroll
        for (int nf = 0; nf < 8; nf++)
            if (nf < nfmax) {
                tm0 = fmaxf(tm0, fmaxf(Sf[nf][0], Sf[nf][1]));
                tm1 = fmaxf(tm1, fmaxf(Sf[nf][2], Sf[nf][3]));
            }
        tm0 = fmaxf(tm0, __shfl_xor_sync(0xffffffffu, tm0, 1));
        tm0 = fmaxf(tm0, __shfl_xor_sync(0xffffffffu, tm0, 2));
        tm1 = fmaxf(tm1, __shfl_xor_sync(0xffffffffu, tm1, 1));
        tm1 = fmaxf(tm1, __shfl_xor_sync(0xffffffffu, tm1, 2));
        float mn0 = fmaxf(m0, tm0), mn1 = fmaxf(m1, tm1);
        float cr0 = __expf(m0 - mn0), cr1 = __expf(m1 - mn1);
        m0 = mn0; m1 = mn1;

        float rs0 = 0.f, rs1 = 0.f;
#pragma unroll
        for (int nf = 0; nf < 8; nf++)
            if (nf < nfmax) {
                float p0 = __expf(Sf[nf][0] - m0);
                float p1 = __expf(Sf[nf][1] - m0);
                float p2 = __expf(Sf[nf][2] - m1);
                float p3 = __expf(Sf[nf][3] - m1);
                rs0 += p0 + p1; rs1 += p2 + p3;
                int c = nf * 8 + 2 * t;
                QPs[r0][c]         = f2tf32(p0);
                QPs[r0][c + 1]     = f2tf32(p1);
                QPs[r0 + 8][c]     = f2tf32(p2);
                QPs[r0 + 8][c + 1] = f2tf32(p3);
            }
        rs0 += __shfl_xor_sync(0xffffffffu, rs0, 1);
        rs0 += __shfl_xor_sync(0xffffffffu, rs0, 2);
        rs1 += __shfl_xor_sync(0xffffffffu, rs1, 1);
        rs1 += __shfl_xor_sync(0xffffffffu, rs1, 2);
        l0 = l0 * cr0 + rs0;
        l1 = l1 * cr1 + rs1;
#pragma unroll
        for (int nf = 0; nf < 8; nf++) {
            Of[nf][0] *= cr0; Of[nf][1] *= cr0;
            Of[nf][2] *= cr1; Of[nf][3] *= cr1;
        }
        __syncwarp();

        int kcmax = diag ? (warp * 2 + 2) : 8;
#pragma unroll
        for (int kc = 0; kc < 8; kc++)
            if (kc < kcmax) {
                uint32_t a0 = QPs[r0][kc * 8 + t];
                uint32_t a1 = QPs[r0 + 8][kc * 8 + t];
                uint32_t a2 = QPs[r0][kc * 8 + t + 4];
                uint32_t a3 = QPs[r0 + 8][kc * 8 + t + 4];
#pragma unroll
                for (int nf = 0; nf < 8; nf++) {
                    uint32_t b0 = Vs[kc * 8 + t][nf * 8 + g];
                    uint32_t b1 = Vs[kc * 8 + t + 4][nf * 8 + g];
                    mma_tf32(Of[nf], a0, a1, a2, a3, b0, b1);
                }
            }
        __syncwarp();
    }

    float il0 = 1.f / l0, il1 = 1.f / l1;
    int b = bh >> 6, n = (bh >> 3) & 7, h = bh & 7;
    int q0 = qb * 64 + warp * 16 + g;
    float* y0 = g_y + ((size_t)(b * Ln + q0) * NG + n) * En + h * HD;
    float* y1 = g_y + ((size_t)(b * Ln + q0 + 8) * NG + n) * En + h * HD;
#pragma unroll
    for (int nf = 0; nf < 8; nf++) {
        int c = nf * 8 + 2 * t;
        *(float2*)(y0 + c) = make_float2(Of[nf][0] * il0, Of[nf][1] * il0);
        *(float2*)(y1 + c) = make_float2(Of[nf][2] * il1, Of[nf][3] * il1);
    }
}

constexpr int ATTN_SMEM = (64 * 68 * 2 + 64 * 72) * 4;   // 53248 bytes

// -------------------------------------------------------------------------
extern "C" void kernel_launch(void* const* d_in, const int* in_sizes, int n_in,
                              void* d_out, int out_size) {
    const float* x      = (const float*)d_in[0];
    const int*   pos    = (const int*)d_in[1];
    const float* w_attn = (const float*)d_in[2];
    const float* b_attn = (const float*)d_in[3];
    const float* w_proj = (const float*)d_in[4];
    const float* b_proj = (const float*)d_in[5];
    float* out = (float*)d_out;

    float *qkv_ptr, *y_ptr;
    cudaGetSymbolAddress((void**)&qkv_ptr, g_qkv);
    cudaGetSymbolAddress((void**)&y_ptr, g_y);
    cudaFuncSetAttribute(attn_mma_kernel,
                         cudaFuncAttributeMaxDynamicSharedMemorySize, ATTN_SMEM);

    // 1) cos/sin table
    rope_tab_kernel<<<(Bn * Ln * 32 + 255) / 256, 256>>>(pos);
    // 2) QKV GEMM (tf32 mma.sync, double-buffered): [16384,512] @ [512,1536]
    mma_gemm_kernel<<<dim3(3 * En / 128, MR / 128), 256>>>(x, w_attn, b_attn,
                                                           qkv_ptr, 3 * En, En);
    // 3) RoPE + transpose into head-major scratch
    rope_transpose_kernel<<<(MR * 256) / 256, 256>>>();
    // 4) tensor-core flash attention: 16 q-blocks x 128 heads
    attn_mma_kernel<<<dim3(Ln / 64, NHEADS), 128, ATTN_SMEM>>>();
    // 5) output projection (tf32 mma.sync, double-buffered): [16384,512] @ [512,512]
    mma_gemm_kernel<<<dim3(En / 128, MR / 128), 256>>>(y_ptr, w_proj, b_proj,
                                                       out, En, En);
}

// round 14
// speedup vs baseline: 3.0444x; 1.1516x over previous
#include <cuda_runtime.h>
#include <math.h>
#include <stdint.h>

// Problem constants
constexpr int Bn = 2;
constexpr int Ln = 1024;
constexpr int NG = 8;
constexpr int En = 512;
constexpr int Hn = 8;
constexpr int HD = 64;
constexpr int MR = Bn * Ln * NG;        // 16384 GEMM rows
constexpr int NHEADS = Bn * NG * Hn;    // 128 attention heads

// Scratch (__device__ globals; no cudaMalloc allowed)
__device__ float g_qkv[(size_t)MR * 3 * En];
__device__ float g_q[(size_t)NHEADS * Ln * HD];
__device__ float g_k[(size_t)NHEADS * Ln * HD];
__device__ float g_v[(size_t)NHEADS * Ln * HD];
__device__ float g_y[(size_t)MR * En];
__device__ float g_cos[Bn * Ln * 32];
__device__ float g_sin[Bn * Ln * 32];

__device__ __forceinline__ uint32_t f2tf32(float x) {
    uint32_t u;
    asm("cvt.rna.tf32.f32 %0, %1;" : "=r"(u) : "f"(x));
    return u;
}
__device__ __forceinline__ void mma_tf32(float c[4], uint32_t a0, uint32_t a1,
                                         uint32_t a2, uint32_t a3,
                                         uint32_t b0, uint32_t b1) {
    asm volatile(
        "mma.sync.aligned.m16n8k8.row.col.f32.tf32.tf32.f32 "
        "{%0,%1,%2,%3}, {%4,%5,%6,%7}, {%8,%9}, {%0,%1,%2,%3};"
        : "+f"(c[0]), "+f"(c[1]), "+f"(c[2]), "+f"(c[3])
        : "r"(a0), "r"(a1), "r"(a2), "r"(a3), "r"(b0), "r"(b1));
}
__device__ __forceinline__ void cp16(uint32_t dst, const float* src) {
    asm volatile("cp.async.ca.shared.global [%0], [%1], 16;"
                 :: "r"(dst), "l"(src));
}

// -------------------------------------------------------------------------
// Kernel 1: RoPE cos/sin table (double-precision trig: exact arg reduction)
// -------------------------------------------------------------------------
__global__ void rope_tab_kernel(const int* __restrict__ pos_ids) {
    int idx = blockIdx.x * blockDim.x + threadIdx.x;
    if (idx >= Bn * Ln * 32) return;
    int d = idx & 31;
    int bl = idx >> 5;
    float inv = (float)exp(-(double)d * (9.210340371976184 / 32.0));
    float ang = (float)pos_ids[bl] * inv;
    g_cos[idx] = (float)cos((double)ang);
    g_sin[idx] = (float)sin((double)ang);
}

// -------------------------------------------------------------------------
// Kernel 2: tf32 mma.sync GEMM, 3-stage cp.async pipeline.
// C[M,Ncols] = A[M,K] @ W[K,Ncols] + bias
// BM=BN=128, BK=16, 256 threads = 8 warps (4 M x 2 N); warp tile 32x64.
// Raw fp32 staged via cp.async; tf32 convert at fragment-load time
// (numerically identical to converting at STS). Conflict-free layouts:
// A[128][20] (bank = 20g+t spans all), B[16][136] (bank = 8t+g).
// One __syncthreads per iter; loads run 2 tiles ahead.
// -------------------------------------------------------------------------
constexpr int AST = 128 * 20;    // floats per A stage
constexpr int BST = 16 * 136;    // floats per B stage
constexpr int GEMM_SMEM = 3 * (AST + BST) * 4;   // 56832 bytes

__global__ __launch_bounds__(256) void mma_gemm_kernel(
    const float* __restrict__ A, const float* __restrict__ W,
    const float* __restrict__ bias, float* __restrict__ C,
    int Ncols, int K)
{
    extern __shared__ float gs[];
    float* Asm = gs;               // 3 stages of [128][20]
    float* Bsm = gs + 3 * AST;     // 3 stages of [16][136]

    int tid = threadIdx.x;
    int bn = blockIdx.x, bm = blockIdx.y;
    const float* Ab = A + (size_t)bm * 128 * K;
    const float* Wb = W + (size_t)bn * 128;

    int aRow = tid >> 2;            // 0..63
    int aCol = (tid & 3) << 2;      // 0,4,8,12
    int bRow = tid >> 5;            // 0..7
    int bCol = (tid & 31) << 2;     // 0..124

    int warp = tid >> 5, lane = tid & 31;
    int wm = warp >> 1, wn = warp & 1;
    int g = lane >> 2, t = lane & 3;
    int rbase = wm * 32, nbase = wn * 64;

    uint32_t aBase = (uint32_t)__cvta_generic_to_shared(Asm);
    uint32_t bBase = (uint32_t)__cvta_generic_to_shared(Bsm);

    float acc[2][8][4];
#pragma unroll
    for (int mf = 0; mf < 2; mf++)
#pragma unroll
        for (int nf = 0; nf < 8; nf++)
#pragma unroll
            for (int i = 0; i < 4; i++) acc[mf][nf][i] = 0.f;

    int nIter = K >> 4;

    // Prologue: stage tiles 0 and 1
#pragma unroll
    for (int s = 0; s < 2; s++) {
        int kt = s * 16;
        cp16(aBase + (uint32_t)(s * AST + aRow * 20 + aCol) * 4,
             Ab + (size_t)aRow * K + kt + aCol);
        cp16(aBase + (uint32_t)(s * AST + (aRow + 64) * 20 + aCol) * 4,
             Ab + (size_t)(aRow + 64) * K + kt + aCol);
        cp16(bBase + (uint32_t)(s * BST + bRow * 136 + bCol) * 4,
             Wb + (size_t)(kt + bRow) * Ncols + bCol);
        cp16(bBase + (uint32_t)(s * BST + (bRow + 8) * 136 + bCol) * 4,
             Wb + (size_t)(kt + bRow + 8) * Ncols + bCol);
        asm volatile("cp.async.commit_group;");
    }

    for (int it = 0; it < nIter; it++) {
        asm volatile("cp.async.wait_group 1;" ::: "memory");
        __syncthreads();

        // Issue tile it+2 into stage (it+2)%3 (freed: consumed at iter it-1,
        // all warps past that via the barrier above)
        if (it + 2 < nIter) {
            int s = (it + 2) % 3;
            int kt = (it + 2) * 16;
            cp16(aBase + (uint32_t)(s * AST + aRow * 20 + aCol) * 4,
                 Ab + (size_t)aRow * K + kt + aCol);
            cp16(aBase + (uint32_t)(s * AST + (aRow + 64) * 20 + aCol) * 4,
                 Ab + (size_t)(aRow + 64) * K + kt + aCol);
            cp16(bBase + (uint32_t)(s * BST + bRow * 136 + bCol) * 4,
                 Wb + (size_t)(kt + bRow) * Ncols + bCol);
            cp16(bBase + (uint32_t)(s * BST + (bRow + 8) * 136 + bCol) * 4,
                 Wb + (size_t)(kt + bRow + 8) * Ncols + bCol);
        }
        asm volatile("cp.async.commit_group;");

        const float* Acur = Asm + (it % 3) * AST;
        const float* Bcur = Bsm + (it % 3) * BST;

#pragma unroll
        for (int ks = 0; ks < 16; ks += 8) {
            uint32_t af[2][4];
#pragma unroll
            for (int mf = 0; mf < 2; mf++) {
                int r0 = rbase + mf * 16 + g;
                af[mf][0] = f2tf32(Acur[r0 * 20 + ks + t]);
                af[mf][1] = f2tf32(Acur[(r0 + 8) * 20 + ks + t]);
                af[mf][2] = f2tf32(Acur[r0 * 20 + ks + t + 4]);
                af[mf][3] = f2tf32(Acur[(r0 + 8) * 20 + ks + t + 4]);
            }
            uint32_t bf[8][2];
#pragma unroll
            for (int nf = 0; nf < 8; nf++) {
                int c0 = nbase + nf * 8 + g;
                bf[nf][0] = f2tf32(Bcur[(ks + t) * 136 + c0]);
                bf[nf][1] = f2tf32(Bcur[(ks + t + 4) * 136 + c0]);
            }
#pragma unroll
            for (int mf = 0; mf < 2; mf++)
#pragma unroll
                for (int nf = 0; nf < 8; nf++)
                    mma_tf32(acc[mf][nf], af[mf][0], af[mf][1], af[mf][2],
                             af[mf][3], bf[nf][0], bf[nf][1]);
        }
    }

#pragma unroll
    for (int mf = 0; mf < 2; mf++) {
        int row0 = bm * 128 + rbase + mf * 16 + g;
#pragma unroll
        for (int nf = 0; nf < 8; nf++) {
            int col = bn * 128 + nbase + nf * 8 + 2 * t;
            float bx = bias[col], by = bias[col + 1];
            float2 o0 = make_float2(acc[mf][nf][0] + bx, acc[mf][nf][1] + by);
            float2 o1 = make_float2(acc[mf][nf][2] + bx, acc[mf][nf][3] + by);
            *(float2*)(C + (size_t)row0 * Ncols + col) = o0;
            *(float2*)(C + (size_t)(row0 + 8) * Ncols + col) = o1;
        }
    }
}

// -------------------------------------------------------------------------
// Kernel 3: RoPE + transpose q,k,v into head-major [bh][l][d]
// -------------------------------------------------------------------------
__global__ __launch_bounds__(256) void rope_transpose_kernel() {
    int idx = blockIdx.x * blockDim.x + threadIdx.x;
    int d = idx & 31;
    int h = (idx >> 5) & 7;
    int r = idx >> 8;
    int n = r & 7;
    int bl = r >> 3;
    int l = bl & (Ln - 1);
    int b = bl >> 10;

    size_t base = (size_t)r * (3 * En) + h * HD;
    float q1 = g_qkv[base + d],          q2 = g_qkv[base + d + 32];
    float k1 = g_qkv[base + En + d],     k2 = g_qkv[base + En + d + 32];
    float v1 = g_qkv[base + 2 * En + d], v2 = g_qkv[base + 2 * En + d + 32];
    float c = g_cos[bl * 32 + d], s = g_sin[bl * 32 + d];

    int bh = (b * NG + n) * Hn + h;
    size_t o = ((size_t)bh * Ln + l) * HD;
    g_q[o + d]      = q1 * c - q2 * s;
    g_q[o + d + 32] = q2 * c + q1 * s;
    g_k[o + d]      = k1 * c - k2 * s;
    g_k[o + d + 32] = k2 * c + k1 * s;
    g_v[o + d]      = v1;
    g_v[o + d + 32] = v2;
}

// -------------------------------------------------------------------------
// Kernel 4: tensor-core causal flash attention (tf32 mma.sync).
// Unchanged from the 236.6us passing version (clean attribution).
// -------------------------------------------------------------------------
__global__ __launch_bounds__(128) void attn_mma_kernel() {
    extern __shared__ uint32_t dynsmem[];
    uint32_t (*QPs)[68] = (uint32_t(*)[68])dynsmem;               // 64x68
    uint32_t (*Ks)[68]  = (uint32_t(*)[68])(dynsmem + 64 * 68);   // 64x68
    uint32_t (*Vs)[72]  = (uint32_t(*)[72])(dynsmem + 2 * 64 * 68); // 64x72

    int qb = blockIdx.x, bh = blockIdx.y;
    int tid = threadIdx.x, warp = tid >> 5, lane = tid & 31;
    int g = lane >> 2, t = lane & 3;

    const float* qp = g_q + ((size_t)bh * Ln + qb * 64) * HD;
    const float* kp = g_k + (size_t)bh * Ln * HD;
    const float* vp = g_v + (size_t)bh * Ln * HD;

    for (int i = tid; i < 64 * 16; i += 128) {
        int row = i >> 4, c = (i & 15) * 4;
        float4 v = *(const float4*)(qp + (size_t)row * HD + c);
        QPs[row][c + 0] = f2tf32(v.x * 0.125f);
        QPs[row][c + 1] = f2tf32(v.y * 0.125f);
        QPs[row][c + 2] = f2tf32(v.z * 0.125f);
        QPs[row][c + 3] = f2tf32(v.w * 0.125f);
    }
    __syncthreads();

    int r0 = warp * 16 + g;
    uint32_t Qf[8][4];
#pragma unroll
    for (int kc = 0; kc < 8; kc++) {
        Qf[kc][0] = QPs[r0][kc * 8 + t];
        Qf[kc][1] = QPs[r0 + 8][kc * 8 + t];
        Qf[kc][2] = QPs[r0][kc * 8 + t + 4];
        Qf[kc][3] = QPs[r0 + 8][kc * 8 + t + 4];
    }

    float Of[8][4];
#pragma unroll
    for (int nf = 0; nf < 8; nf++)
#pragma unroll
        for (int i = 0; i < 4; i++) Of[nf][i] = 0.f;
    float m0 = -1e30f, m1 = -1e30f, l0 = 0.f, l1 = 0.f;

    for (int kb = 0; kb <= qb; kb++) {
        __syncthreads();
        for (int i = tid; i < 64 * 16; i += 128) {
            int row = i >> 4, c = (i & 15) * 4;
            float4 kv = *(const float4*)(kp + (size_t)(kb * 64 + row) * HD + c);
            float4 vv = *(const float4*)(vp + (size_t)(kb * 64 + row) * HD + c);
            Ks[row][c + 0] = f2tf32(kv.x); Ks[row][c + 1] = f2tf32(kv.y);
            Ks[row][c + 2] = f2tf32(kv.z); Ks[row][c + 3] = f2tf32(kv.w);
            Vs[row][c + 0] = f2tf32(vv.x); Vs[row][c + 1] = f2tf32(vv.y);
            Vs[row][c + 2] = f2tf32(vv.z); Vs[row][c + 3] = f2tf32(vv.w);
        }
        __syncthreads();

        bool diag = (kb == qb);
        int nfmax = diag ? (warp * 2 + 2) : 8;

        float Sf[8][4];
#pragma unroll
        for (int nf = 0; nf < 8; nf++) {
            if (nf < nfmax) {
                Sf[nf][0] = 0.f; Sf[nf][1] = 0.f; Sf[nf][2] = 0.f; Sf[nf][3] = 0.f;
#pragma unroll
                for (int kc = 0; kc < 8; kc++) {
                    uint32_t b0 = Ks[nf * 8 + g][kc * 8 + t];
                    uint32_t b1 = Ks[nf * 8 + g][kc * 8 + t + 4];
                    mma_tf32(Sf[nf], Qf[kc][0], Qf[kc][1], Qf[kc][2], Qf[kc][3],
                             b0, b1);
                }
                if (diag) {
                    int rl0 = warp * 16 + g, rl1 = rl0 + 8, c0 = nf * 8 + 2 * t;
                    if (c0 > rl0)     Sf[nf][0] = -1e30f;
                    if (c0 + 1 > rl0) Sf[nf][1] = -1e30f;
                    if (c0 > rl1)     Sf[nf][2] = -1e30f;
                    if (c0 + 1 > rl1) Sf[nf][3] = -1e30f;
                }
            }
        }

        float tm0 = -1e30f, tm1 = -1e30f;
#pragma unroll
        for (int nf = 0; nf < 8; nf++)
            if (nf < nfmax) {
                tm0 = fmaxf(tm0, fmaxf(Sf[nf][0], Sf[nf][1]));
                tm1 = fmaxf(tm1, fmaxf(Sf[nf][2], Sf[nf][3]));
            }
        tm0 = fmaxf(tm0, __shfl_xor_sync(0xffffffffu, tm0, 1));
        tm0 = fmaxf(tm0, __shfl_xor_sync(0xffffffffu, tm0, 2));
        tm1 = fmaxf(tm1, __shfl_xor_sync(0xffffffffu, tm1, 1));
        tm1 = fmaxf(tm1, __shfl_xor_sync(0xffffffffu, tm1, 2));
        float mn0 = fmaxf(m0, tm0), mn1 = fmaxf(m1, tm1);
        float cr0 = __expf(m0 - mn0), cr1 = __expf(m1 - mn1);
        m0 = mn0; m1 = mn1;

        float rs0 = 0.f, rs1 = 0.f;
#pragma unroll
        for (int nf = 0; nf < 8; nf++)
            if (nf < nfmax) {
                float p0 = __expf(Sf[nf][0] - m0);
                float p1 = __expf(Sf[nf][1] - m0);
                float p2 = __expf(Sf[nf][2] - m1);
                float p3 = __expf(Sf[nf][3] - m1);
                rs0 += p0 + p1; rs1 += p2 + p3;
                int c = nf * 8 + 2 * t;
                QPs[r0][c]         = f2tf32(p0);
                QPs[r0][c + 1]     = f2tf32(p1);
                QPs[r0 + 8][c]     = f2tf32(p2);
                QPs[r0 + 8][c + 1] = f2tf32(p3);
            }
        rs0 += __shfl_xor_sync(0xffffffffu, rs0, 1);
        rs0 += __shfl_xor_sync(0xffffffffu, rs0, 2);
        rs1 += __shfl_xor_sync(0xffffffffu, rs1, 1);
        rs1 += __shfl_xor_sync(0xffffffffu, rs1, 2);
        l0 = l0 * cr0 + rs0;
        l1 = l1 * cr1 + rs1;
#pragma unroll
        for (int nf = 0; nf < 8; nf++) {
            Of[nf][0] *= cr0; Of[nf][1] *= cr0;
            Of[nf][2] *= cr1; Of[nf][3] *= cr1;
        }
        __syncwarp();

        int kcmax = diag ? (warp * 2 + 2) : 8;
#pragma unroll
        for (int kc = 0; kc < 8; kc++)
            if (kc < kcmax) {
                uint32_t a0 = QPs[r0][kc * 8 + t];
                uint32_t a1 = QPs[r0 + 8][kc * 8 + t];
                uint32_t a2 = QPs[r0][kc * 8 + t + 4];
                uint32_t a3 = QPs[r0 + 8][kc * 8 + t + 4];
#pragma unroll
                for (int nf = 0; nf < 8; nf++) {
                    uint32_t b0 = Vs[kc * 8 + t][nf * 8 + g];
                    uint32_t b1 = Vs[kc * 8 + t + 4][nf * 8 + g];
                    mma_tf32(Of[nf], a0, a1, a2, a3, b0, b1);
                }
            }
        __syncwarp();
    }

    float il0 = 1.f / l0, il1 = 1.f / l1;
    int b = bh >> 6, n = (bh >> 3) & 7, h = bh & 7;
    int q0 = qb * 64 + warp * 16 + g;
    float* y0 = g_y + ((size_t)(b * Ln + q0) * NG + n) * En + h * HD;
    float* y1 = g_y + ((size_t)(b * Ln + q0 + 8) * NG + n) * En + h * HD;
#pragma unroll
    for (int nf = 0; nf < 8; nf++) {
        int c = nf * 8 + 2 * t;
        *(float2*)(y0 + c) = make_float2(Of[nf][0] * il0, Of[nf][1] * il0);
        *(float2*)(y1 + c) = make_float2(Of[nf][2] * il1, Of[nf][3] * il1);
    }
}

constexpr int ATTN_SMEM = (64 * 68 * 2 + 64 * 72) * 4;   // 53248 bytes

// -------------------------------------------------------------------------
extern "C" void kernel_launch(void* const* d_in, const int* in_sizes, int n_in,
                              void* d_out, int out_size) {
    const float* x      = (const float*)d_in[0];
    const int*   pos    = (const int*)d_in[1];
    const float* w_attn = (const float*)d_in[2];
    const float* b_attn = (const float*)d_in[3];
    const float* w_proj = (const float*)d_in[4];
    const float* b_proj = (const float*)d_in[5];
    float* out = (float*)d_out;

    float *qkv_ptr, *y_ptr;
    cudaGetSymbolAddress((void**)&qkv_ptr, g_qkv);
    cudaGetSymbolAddress((void**)&y_ptr, g_y);
    cudaFuncSetAttribute(attn_mma_kernel,
                         cudaFuncAttributeMaxDynamicSharedMemorySize, ATTN_SMEM);
    cudaFuncSetAttribute(mma_gemm_kernel,
                         cudaFuncAttributeMaxDynamicSharedMemorySize, GEMM_SMEM);

    // 1) cos/sin table
    rope_tab_kernel<<<(Bn * Ln * 32 + 255) / 256, 256>>>(pos);
    // 2) QKV GEMM (tf32 mma.sync, 3-stage cp.async): [16384,512] @ [512,1536]
    mma_gemm_kernel<<<dim3(3 * En / 128, MR / 128), 256, GEMM_SMEM>>>(
        x, w_attn, b_attn, qkv_ptr, 3 * En, En);
    // 3) RoPE + transpose into head-major scratch
    rope_transpose_kernel<<<(MR * 256) / 256, 256>>>();
    // 4) tensor-core flash attention: 16 q-blocks x 128 heads
    attn_mma_kernel<<<dim3(Ln / 64, NHEADS), 128, ATTN_SMEM>>>();
    // 5) output projection (tf32 mma.sync, 3-stage cp.async): [16384,512] @ [512,512]
    mma_gemm_kernel<<<dim3(En / 128, MR / 128), 256, GEMM_SMEM>>>(
        y_ptr, w_proj, b_proj, out, En, En);
}